// round 10
// baseline (speedup 1.0000x reference)
#include <cuda_runtime.h>
#include <cstdint>

// PixelPrototypeDistanceLoss — B=8, D=256, H=W=128, C=19, IGNORE=19
// loss = mean over valid pixels of (1 - emb[b,:,h,w] . Q[lb]) ^ 2
//
// R10: cp.async.cg pipeline (R9 post-mortem: in-flight bytes tripled across
// R4->R9 with ZERO BW gain -> register-scoreboard path caps effective LDG depth
// at ~2. LDGSTS groups guarantee depth: 3-stage x 4-plane SMEM ring, 2 groups
// (8 planes, 4KB/warp) always outstanding, no scoreboard, no dead phases).
//  - grid 512 x 128 thr: CTA = 256 px (64 float4 groups) x full D;
//    thread = (pg 0..63, d-half 0/1), consumes its own SMEM slots only ->
//    no __syncthreads in the pipeline.
//  - Q in SMEM stride 257 (conflict-free gather)
//  - fused last-block-done reduction (counter self-rearms; no spin-waits)
//
// lb is int32 on device (JAX x64 disabled).

constexpr int Bv = 8, Dv = 256, Hv = 128, Wv = 128, Cv = 19, IGNORE = 19;
constexpr int HW = Hv * Wv;                     // 16384
constexpr int HW4 = HW / 4;                     // 4096 float4-groups per plane
constexpr long long NPIX = (long long)Bv * HW;  // 131072
constexpr int THREADS = 128;                    // 64 pg x 2 d-halves
constexpr int PG = 64;                          // float4 groups per CTA (256 px)
constexpr int NBLOCKS = (int)(NPIX / (4 * PG)); // 512
constexpr int QSTRIDE = Dv + 1;                 // 257
constexpr int DHALF = Dv / 2;                   // 128 d per half
constexpr int NB = 4;                           // planes per async group
constexpr int STAGES = 3;                       // ring depth (2 groups in flight)
constexpr int NCH = DHALF / NB;                 // 32 chunks

__device__ float g_bsum[NBLOCKS];
__device__ float g_bcnt[NBLOCKS];
__device__ unsigned int g_count = 0;            // rearmed by last block each launch

__device__ __forceinline__ void cpa16(uint32_t smem_dst, const void* gmem_src) {
    asm volatile("cp.async.cg.shared.global [%0], [%1], 16;"
                 :: "r"(smem_dst), "l"(gmem_src));
}
__device__ __forceinline__ void cpa_commit() {
    asm volatile("cp.async.commit_group;");
}
template <int N>
__device__ __forceinline__ void cpa_wait() {
    asm volatile("cp.async.wait_group %0;" :: "n"(N));
}

__global__ void __launch_bounds__(THREADS, 4)
ppd_fused(const float4* __restrict__ emb4,
          const int4* __restrict__ lb4,
          const float* __restrict__ Q,
          float* __restrict__ out) {
    __shared__ float4 buf[STAGES * NB * THREADS];   // 24 KB ring
    __shared__ float Qs[Cv * QSTRIDE];              // ~19.5 KB
    __shared__ float s_part[PG * 4];                // 1 KB upper-half partials
    __shared__ float s_sq[2];
    __shared__ float s_ct[2];
    __shared__ double sh_s[4];
    __shared__ double sh_k[4];
    __shared__ int s_last;

    const int tid  = threadIdx.x;
    const int pg   = tid & (PG - 1);            // 0..63
    const int half = tid >> 6;                  // 0/1

    const int t4 = blockIdx.x * PG + pg;        // global float4-group id
    const int4 lbv = lb4[t4];
    const bool v0 = lbv.x != IGNORE, v1 = lbv.y != IGNORE,
               v2 = lbv.z != IGNORE, v3 = lbv.w != IGNORE;

    // Stage Q [19,256] -> padded SMEM
    for (int i = tid; i < Cv * Dv; i += THREADS) {
        const int cc = i >> 8;
        const int dd = i & (Dv - 1);
        Qs[cc * QSTRIDE + dd] = Q[i];
    }
    __syncthreads();

    const float* q0 = &Qs[(v0 ? lbv.x : 0) * QSTRIDE];
    const float* q1 = &Qs[(v1 ? lbv.y : 0) * QSTRIDE];
    const float* q2 = &Qs[(v2 ? lbv.z : 0) * QSTRIDE];
    const float* q3 = &Qs[(v3 ? lbv.w : 0) * QSTRIDE];

    const int b    = blockIdx.x >> 6;           // 64 CTAs per image
    const int hw4  = (blockIdx.x & 63) * PG + pg;
    const int dbase = half * DHALF;
    const float4* ep = emb4 + ((long long)b * Dv + dbase) * HW4 + hw4;

    // per-thread SMEM slots (generic->shared u32 addressing)
    const uint32_t buf_base =
        (uint32_t)__cvta_generic_to_shared(&buf[0]) + tid * (uint32_t)sizeof(float4);
    auto slot = [&](int stage, int j) -> uint32_t {
        return buf_base + (uint32_t)((stage * NB + j) * THREADS) * (uint32_t)sizeof(float4);
    };

    float a0 = 0.f, a1 = 0.f, a2 = 0.f, a3 = 0.f;

    // prologue: fill stages 0 and 1 (groups g0, g1)
#pragma unroll
    for (int s = 0; s < 2; ++s) {
#pragma unroll
        for (int j = 0; j < NB; ++j)
            cpa16(slot(s, j), ep + (long long)(s * NB + j) * HW4);
        cpa_commit();
    }

#pragma unroll
    for (int c = 0; c < NCH; ++c) {
        // prefetch chunk c+2 into stage (c+2)%3
        if (c + 2 < NCH) {
            const int s = (c + 2) % STAGES;
#pragma unroll
            for (int j = 0; j < NB; ++j)
                cpa16(slot(s, j), ep + (long long)((c + 2) * NB + j) * HW4);
            cpa_commit();
        }
        // wait so that chunk c's group is retired
        if (c + 2 < NCH)      cpa_wait<2>();
        else if (c + 1 < NCH) cpa_wait<1>();
        else                  cpa_wait<0>();

        const int s = c % STAGES;
#pragma unroll
        for (int j = 0; j < NB; ++j) {
            const float4 v = buf[(s * NB + j) * THREADS + tid];  // own slot, LDS.128
            const int d = dbase + c * NB + j;
            a0 = fmaf(v.x, q0[d], a0);
            a1 = fmaf(v.y, q1[d], a1);
            a2 = fmaf(v.z, q2[d], a2);
            a3 = fmaf(v.w, q3[d], a3);
        }
    }

    // combine d-halves
    if (half == 1) {
        s_part[pg * 4 + 0] = a0;
        s_part[pg * 4 + 1] = a1;
        s_part[pg * 4 + 2] = a2;
        s_part[pg * 4 + 3] = a3;
    }
    __syncthreads();

    const int wid  = tid >> 5;
    const int lane = tid & 31;

    if (half == 0) {                            // warps 0-1 finish the loss
        a0 += s_part[pg * 4 + 0];
        a1 += s_part[pg * 4 + 1];
        a2 += s_part[pg * 4 + 2];
        a3 += s_part[pg * 4 + 3];

        const float r0 = 1.f - a0, r1 = 1.f - a1, r2 = 1.f - a2, r3 = 1.f - a3;
        float sq  = (v0 ? r0 * r0 : 0.f) + (v1 ? r1 * r1 : 0.f)
                  + (v2 ? r2 * r2 : 0.f) + (v3 ? r3 * r3 : 0.f);
        float cnt = (float)v0 + (float)v1 + (float)v2 + (float)v3;

#pragma unroll
        for (int o = 16; o > 0; o >>= 1) {
            sq  += __shfl_down_sync(0xFFFFFFFFu, sq,  o);
            cnt += __shfl_down_sync(0xFFFFFFFFu, cnt, o);
        }
        if (lane == 0) { s_sq[wid] = sq; s_ct[wid] = cnt; }
    }
    __syncthreads();

    if (tid == 0) {
        g_bsum[blockIdx.x] = s_sq[0] + s_sq[1];
        g_bcnt[blockIdx.x] = s_ct[0] + s_ct[1];
        __threadfence();
        const unsigned prev = atomicAdd(&g_count, 1u);
        s_last = (prev == (unsigned)(NBLOCKS - 1));
    }
    __syncthreads();

    if (s_last) {                               // last block reduces 512 partials
        double a = 0.0, k = 0.0;
        for (int i = tid; i < NBLOCKS; i += THREADS) {
            a += (double)__ldcg(&g_bsum[i]);
            k += (double)__ldcg(&g_bcnt[i]);
        }
#pragma unroll
        for (int o = 16; o > 0; o >>= 1) {
            a += __shfl_down_sync(0xFFFFFFFFu, a, o);
            k += __shfl_down_sync(0xFFFFFFFFu, k, o);
        }
        if (lane == 0) { sh_s[wid] = a; sh_k[wid] = k; }
        __syncthreads();
        if (wid == 0) {
            double aa = (lane < 4) ? sh_s[lane] : 0.0;
            double kk = (lane < 4) ? sh_k[lane] : 0.0;
#pragma unroll
            for (int o = 2; o > 0; o >>= 1) {
                aa += __shfl_down_sync(0xFFFFFFFFu, aa, o);
                kk += __shfl_down_sync(0xFFFFFFFFu, kk, o);
            }
            if (lane == 0) {
                out[0] = (float)(aa / kk);
                g_count = 0;                    // rearm for next replay
            }
        }
    }
}

extern "C" void kernel_launch(void* const* d_in, const int* in_sizes, int n_in,
                              void* d_out, int out_size) {
    const float4* emb = (const float4*)d_in[0]; // [8,256,128,128] f32
    const int4*   lb  = (const int4*)d_in[1];   // [8,128,128] i32
    const float*  Q   = (const float*)d_in[2];  // [19,256] f32
    float*        out = (float*)d_out;          // scalar f32

    (void)in_sizes; (void)n_in; (void)out_size;

    ppd_fused<<<NBLOCKS, THREADS>>>(emb, lb, Q, out);
}